// round 6
// baseline (speedup 1.0000x reference)
#include <cuda_runtime.h>
#include <cuda_fp16.h>
#include <cstdint>

// FastSNN: fp32 GEMM via 2-term fp16 split x 3 products (a0b0+a0b1+a1b0),
// mma.sync m16n8k16 + ldmatrix. Product-pass-outermost MMA ordering to break
// accumulator RAW chains. Then LIF scan + decoder.
// proj[m,f] = sum_w X[m,w]*Wt[f,w], M=64000, N(F)=512, K(W)=256.

#define TT 500
#define BB 128
#define WW 256
#define FF 512
#define CC 10
#define MM (TT * BB)

__device__ float g_proj[(size_t)MM * FF];   // 131 MB scratch

#define RSTR 80
#define MATB (128 * RSTR)
#define STAGEB (2 * MATB)             // 20480 B per stage

__device__ __forceinline__ uint32_t smem_u32(const void* p) {
    uint32_t a;
    asm("{ .reg .u64 t; cvta.to.shared.u64 t, %1; cvt.u32.u64 %0, t; }" : "=r"(a) : "l"(p));
    return a;
}

#define LDSM_X4(r0, r1, r2, r3, addr) \
    asm volatile("ldmatrix.sync.aligned.m8n8.x4.shared.b16 {%0,%1,%2,%3}, [%4];" \
        : "=r"(r0), "=r"(r1), "=r"(r2), "=r"(r3) : "r"(addr))

#define MMA_F16(c, a, b) \
    asm volatile( \
        "mma.sync.aligned.m16n8k16.row.col.f32.f16.f16.f32 " \
        "{%0,%1,%2,%3}, {%4,%5,%6,%7}, {%8,%9}, {%0,%1,%2,%3};" \
        : "+f"((c)[0]), "+f"((c)[1]), "+f"((c)[2]), "+f"((c)[3]) \
        : "r"((a)[0]), "r"((a)[1]), "r"((a)[2]), "r"((a)[3]), \
          "r"((b)[0]), "r"((b)[1]))

__device__ __forceinline__ void cvt8(const float4 v0, const float4 v1,
                                     uint4& big, uint4& small) {
    float v[8] = {v0.x, v0.y, v0.z, v0.w, v1.x, v1.y, v1.z, v1.w};
    __half hb[8], hs[8];
#pragma unroll
    for (int j = 0; j < 8; j++) {
        hb[j] = __float2half_rn(v[j]);
        hs[j] = __float2half_rn(v[j] - __half2float(hb[j]));
    }
    __half2 b2[4], s2[4];
#pragma unroll
    for (int j = 0; j < 4; j++) {
        b2[j] = __halves2half2(hb[2*j], hb[2*j+1]);
        s2[j] = __halves2half2(hs[2*j], hs[2*j+1]);
    }
    big   = make_uint4(*(uint32_t*)&b2[0], *(uint32_t*)&b2[1],
                       *(uint32_t*)&b2[2], *(uint32_t*)&b2[3]);
    small = make_uint4(*(uint32_t*)&s2[0], *(uint32_t*)&s2[1],
                       *(uint32_t*)&s2[2], *(uint32_t*)&s2[3]);
}

// ---------------------------------------------------------------------------
// GEMM: CTA 128x128, BK=16, 8 warps (2m x 4n), warp tile 64x32, double-buffer.
// ---------------------------------------------------------------------------
__global__ __launch_bounds__(256, 2)
void gemm_fp16_kernel(const float* __restrict__ X, const float* __restrict__ Wt) {
    __shared__ __align__(128) char sm[2 * STAGEB];   // 40 KB

    const int tid  = threadIdx.x;
    const int lane = tid & 31;
    const int wid  = tid >> 5;
    const int warp_m = wid & 1;
    const int warp_n = wid >> 1;
    const int m0 = blockIdx.y * 128;
    const int n0 = blockIdx.x * 128;

    const uint32_t sbase = smem_u32(sm);

    const int rowC = tid >> 1;
    const int kh   = tid & 1;
    const float* gA = X  + (size_t)(m0 + rowC) * WW + kh * 8;
    const float* gB = Wt + (size_t)(n0 + rowC) * WW + kh * 8;
    const uint32_t stoA = rowC * RSTR + kh * 16;
    const uint32_t stoB = MATB + stoA;

    const uint32_t lrow  = lane & 15;
    const uint32_t lkoff = ((lane >> 4) & 1) * 16;
    const uint32_t aAddr0 = (warp_m * 64 + lrow) * RSTR + lkoff;
    const uint32_t bAddr0 = MATB + (warp_n * 32 + lrow) * RSTR + lkoff;

    float acc[4][4][4];
#pragma unroll
    for (int mt = 0; mt < 4; mt++)
#pragma unroll
        for (int nt = 0; nt < 4; nt++)
#pragma unroll
            for (int q = 0; q < 4; q++) acc[mt][nt][q] = 0.0f;

    {
        float4 a0 = *(const float4*)(gA);
        float4 a1 = *(const float4*)(gA + 4);
        float4 b0 = *(const float4*)(gB);
        float4 b1 = *(const float4*)(gB + 4);
        uint4 big, small;
        cvt8(a0, a1, big, small);
        *(uint4*)(sm + stoA)      = big;
        *(uint4*)(sm + stoA + 32) = small;
        cvt8(b0, b1, big, small);
        *(uint4*)(sm + stoB)      = big;
        *(uint4*)(sm + stoB + 32) = small;
    }
    __syncthreads();

    int buf = 0;
#pragma unroll 1
    for (int kt = 0; kt < 16; kt++) {
        const bool more = (kt < 15);
        float4 pa0, pa1, pb0, pb1;
        if (more) {
            const int ko = (kt + 1) * 16;
            pa0 = *(const float4*)(gA + ko);
            pa1 = *(const float4*)(gA + ko + 4);
            pb0 = *(const float4*)(gB + ko);
            pb1 = *(const float4*)(gB + ko + 4);
        }

        const uint32_t sb = sbase + buf * STAGEB;

        uint32_t ab[4][4], as_[4][4], bb[4][2], bs[4][2];
#pragma unroll
        for (int mt = 0; mt < 4; mt++) {
            const uint32_t ad = sb + aAddr0 + mt * 16 * RSTR;
            LDSM_X4(ab[mt][0],  ab[mt][1],  ab[mt][2],  ab[mt][3],  ad);
            LDSM_X4(as_[mt][0], as_[mt][1], as_[mt][2], as_[mt][3], ad + 32);
        }
#pragma unroll
        for (int p = 0; p < 2; p++) {
            const uint32_t bd = sb + bAddr0 + p * 16 * RSTR;
            uint32_t r0, r1, r2, r3;
            LDSM_X4(r0, r1, r2, r3, bd);
            bb[2*p][0] = r0; bb[2*p][1] = r2;
            bb[2*p+1][0] = r1; bb[2*p+1][1] = r3;
            LDSM_X4(r0, r1, r2, r3, bd + 32);
            bs[2*p][0] = r0; bs[2*p][1] = r2;
            bs[2*p+1][0] = r1; bs[2*p+1][1] = r3;
        }

        // Product-pass outermost: consecutive MMAs never share an accumulator
        // (reuse distance 16) -> latency hidden even at low warp count.
#pragma unroll
        for (int mt = 0; mt < 4; mt++)
#pragma unroll
            for (int nt = 0; nt < 4; nt++)
                MMA_F16(acc[mt][nt], ab[mt],  bb[nt]);
#pragma unroll
        for (int mt = 0; mt < 4; mt++)
#pragma unroll
            for (int nt = 0; nt < 4; nt++)
                MMA_F16(acc[mt][nt], ab[mt],  bs[nt]);
#pragma unroll
        for (int mt = 0; mt < 4; mt++)
#pragma unroll
            for (int nt = 0; nt < 4; nt++)
                MMA_F16(acc[mt][nt], as_[mt], bb[nt]);

        if (more) {
            char* d = sm + (buf ^ 1) * STAGEB;
            uint4 big, small;
            cvt8(pa0, pa1, big, small);
            *(uint4*)(d + stoA)      = big;
            *(uint4*)(d + stoA + 32) = small;
            cvt8(pb0, pb1, big, small);
            *(uint4*)(d + stoB)      = big;
            *(uint4*)(d + stoB + 32) = small;
        }
        __syncthreads();
        buf ^= 1;
    }

#pragma unroll
    for (int mt = 0; mt < 4; mt++) {
#pragma unroll
        for (int nt = 0; nt < 4; nt++) {
            const int r = m0 + warp_m * 64 + mt * 16 + (lane >> 2);
            const int c = n0 + warp_n * 32 + nt * 8 + (lane & 3) * 2;
            *reinterpret_cast<float2*>(&g_proj[(size_t)r * FF + c]) =
                make_float2(acc[mt][nt][0], acc[mt][nt][1]);
            *reinterpret_cast<float2*>(&g_proj[(size_t)(r + 8) * FF + c]) =
                make_float2(acc[mt][nt][2], acc[mt][nt][3]);
        }
    }
}

// ---------------------------------------------------------------------------
// LIF scan + fused decoder. MLP=25 streaming loads.
// ---------------------------------------------------------------------------
__global__ __launch_bounds__(512)
void scan_decoder_kernel(const float* __restrict__ dec_w,
                         const float* __restrict__ dec_b,
                         float* __restrict__ out) {
    const int b = blockIdx.x;
    const int f = threadIdx.x;
    const float* pp = g_proj + (size_t)b * FF + f;

    float u = 0.0f, trace = 0.0f, cnt = 0.0f;

#pragma unroll 1
    for (int t0 = 0; t0 < TT; t0 += 25) {
        float v[25];
#pragma unroll
        for (int i = 0; i < 25; i++)
            v[i] = __ldcg(pp + (size_t)(t0 + i) * (BB * FF));
#pragma unroll
        for (int i = 0; i < 25; i++) {
            trace = 0.95f * trace + v[i];
            u = 0.9f * u + trace;
            if (u > 1.0f) { cnt += 1.0f; u = 0.0f; }
        }
    }

    __shared__ float sred[512];
    for (int c = 0; c < CC; c++) {
        sred[f] = cnt * dec_w[c * FF + f];
        __syncthreads();
#pragma unroll
        for (int s = 256; s > 0; s >>= 1) {
            if (f < s) sred[f] += sred[f + s];
            __syncthreads();
        }
        if (f == 0) out[b * CC + c] = sred[0] + dec_b[c];
        __syncthreads();
    }
}

// ---------------------------------------------------------------------------
extern "C" void kernel_launch(void* const* d_in, const int* in_sizes, int n_in,
                              void* d_out, int out_size) {
    const float* x     = (const float*)d_in[0];  // [500,128,256]
    const float* wts   = (const float*)d_in[1];  // [512,256]
    const float* dec_w = (const float*)d_in[2];  // [10,512]
    const float* dec_b = (const float*)d_in[3];  // [10]
    float* out = (float*)d_out;                  // [128,10]
    (void)in_sizes; (void)n_in; (void)out_size;

    dim3 grid(FF / 128, MM / 128);   // (4, 500)
    gemm_fp16_kernel<<<grid, 256>>>(x, wts);

    scan_decoder_kernel<<<BB, 512>>>(dec_w, dec_b, out);
}